// round 16
// baseline (speedup 1.0000x reference)
#include <cuda_runtime.h>
#include <cuda_fp16.h>

#define IW   512
#define NB   4
#define NT   180
#define NTH  90             // sampled angles; 90..179 via row sums
#define PAD  16
#define PW   (IW + 2*PAD)   // 544 = 17*32
#define NCH  4
#define HCH  (IW / NCH)     // 128
#define NWT  8
#define IMG_STRIDE (IW*IW)
#define OFS  ((float)PAD + 255.5f)     // padded-center offset
#define LO   ((float)PAD - 1.0f)       // nonzero support lower edge
#define HI   ((float)PAD + 512.0f)     // nonzero support upper edge

// 32B entry at (r,c): full 2x2 bilinear stencil x 4 batches, fp16.
struct __align__(32) E32 { uint4 t, b; };

__device__ E32   g_pair [PW * PW];                 // 9.5 MB
__device__ E32   g_pairT[PW * PW];                 // 9.5 MB
__device__ float4 g_colpart[NCH][NTH][IW];         // batches packed per entry
__device__ uint2  g_rowpart[NTH][NWT][IW];         // half4 per (t,wt,h)

// 256-bit global load (sm_100+)
__device__ __forceinline__ void ldg256(const E32* p, uint4& t, uint4& b) {
    asm("ld.global.v8.b32 {%0,%1,%2,%3,%4,%5,%6,%7}, [%8];"
        : "=r"(t.x), "=r"(t.y), "=r"(t.z), "=r"(t.w),
          "=r"(b.x), "=r"(b.y), "=r"(b.z), "=r"(b.w)
        : "l"(p));
}

// ---------------------------------------------------------------------------
// Tiled prep, 1024 threads: one 32x32-entry tile per block (covers the whole
// padded image; borders become zeros via pixel clamp). Pixels staged once in
// smem; each thread writes exactly one normal and one transposed entry.
// ---------------------------------------------------------------------------
__global__ __launch_bounds__(1024) void prep_kernel(const float* __restrict__ x) {
    __shared__ float s[4][33 * 33];     // 17.4 KB

    const int Rp0 = blockIdx.y * 32;    // padded-row tile origin
    const int Cp0 = blockIdx.x * 32;    // padded-col tile origin
    const int pr0 = Rp0 - PAD;          // pixel-row of smem row 0
    const int pc0 = Cp0 - PAD;
    const int tid = threadIdx.x;

    // stage 33x33 pixel window x 4 batches (zero-clamped), coalesced reads
    for (int k = tid; k < 33 * 33; k += 1024) {
        const int i = k / 33;
        const int j = k - i * 33;
        const int pr = pr0 + i;
        const int pc = pc0 + j;
        const bool v = (unsigned)pr < (unsigned)IW && (unsigned)pc < (unsigned)IW;
        const int off = pr * IW + pc;
        #pragma unroll
        for (int b = 0; b < 4; ++b)
            s[b][k] = v ? x[off + b * IMG_STRIDE] : 0.f;
    }
    __syncthreads();

    // normal-orientation entry: (i, j), j fastest (coalesced 32B writes)
    {
        const int i = tid >> 5, j = tid & 31;
        E32 en;
        #pragma unroll
        for (int b = 0; b < 4; ++b) {
            const float p00 = s[b][i * 33 + j];
            const float p01 = s[b][i * 33 + j + 1];
            const float p10 = s[b][(i + 1) * 33 + j];
            const float p11 = s[b][(i + 1) * 33 + j + 1];
            __half2 nt = __floats2half2_rn(p00, p01);
            __half2 nb = __floats2half2_rn(p10, p11);
            ((unsigned*)&en.t)[b] = *(unsigned*)&nt;
            ((unsigned*)&en.b)[b] = *(unsigned*)&nb;
        }
        g_pair[(Rp0 + i) * PW + (Cp0 + j)] = en;
    }

    // transposed-orientation entry: (j, i), i fastest (coalesced writes;
    // smem stride-33 reads are bank-conflict-free)
    {
        const int j = tid >> 5, i = tid & 31;
        E32 et;
        #pragma unroll
        for (int b = 0; b < 4; ++b) {
            const float p00 = s[b][i * 33 + j];
            const float p01 = s[b][i * 33 + j + 1];
            const float p10 = s[b][(i + 1) * 33 + j];
            const float p11 = s[b][(i + 1) * 33 + j + 1];
            __half2 tt = __floats2half2_rn(p00, p10);
            __half2 tb = __floats2half2_rn(p01, p11);
            ((unsigned*)&et.t)[b] = *(unsigned*)&tt;
            ((unsigned*)&et.b)[b] = *(unsigned*)&tb;
        }
        g_pairT[(Cp0 + j) * PW + (Rp0 + i)] = et;
    }
}

// ---------------------------------------------------------------------------
// Radon for t in 0..89; column sums -> P_t, row sums -> P_{t+90} (mirrored).
// ---------------------------------------------------------------------------
__global__ __launch_bounds__(256, 6) void radon_kernel(const float* __restrict__ theta) {
    __shared__ uint2 s_row[8][HCH][4];   // 32 KB

    const int t    = blockIdx.x;
    const int wt   = blockIdx.y;
    const int ch   = blockIdx.z;
    const int tid  = threadIdx.x;
    const int warp = tid >> 5;
    const int lane = tid & 31;
    const int wl   = lane & 7;
    const int hl   = lane >> 3;
    const int w    = wt * 64 + warp * 8 + wl;

    // zero row-partial slab (skipped k's must read as 0)
    {
        uint4* sr = (uint4*)&s_row[0][0][0];
        #pragma unroll
        for (int i = 0; i < 8; ++i)
            sr[tid + 256 * i] = make_uint4(0u, 0u, 0u, 0u);
    }
    __syncthreads();

    const float rad = theta[t] * 0.017453292519943295f;
    float s, c;
    sincosf(rad, &s, &c);

    float cA, sA, cB, sB;
    const E32* __restrict__ img;
    if (fabsf(s) > fabsf(c)) { cA = -s; sA = c; cB = c;  sB = s; img = g_pairT; }
    else                     { cA = c;  sA = s; cB = -s; sB = c; img = g_pair;  }

    const float wf    = (float)w - 255.5f;
    const float colw  = fmaf(cA, wf, OFS);
    const float roww  = fmaf(cB, wf, OFS);
    const float hbase = (float)(ch * HCH) - 255.5f;

    // warp-uniform valid-k interval (nonzero bilinear support: coord in (LO, HI))
    const float wfa = (float)(wt * 64 + warp * 8) - 255.5f;
    const float wfb = wfa + 7.0f;
    float t1a = cB * wfa, t1b = cB * wfb;
    const float rA = OFS + fminf(t1a, t1b);
    const float rB = OFS + fmaxf(t1a, t1b) + 3.0f * sB;
    const float rh = sB * hbase;
    const float inv4sB = 1.0f / (4.0f * sB);
    float kL = (LO - rB - rh) * inv4sB;
    float kU = (HI - rA - rh) * inv4sB;
    float t2a = cA * wfa, t2b = cA * wfb;
    const float cC = OFS + fminf(t2a, t2b) + fminf(0.f, 3.f * sA);
    const float cD = OFS + fmaxf(t2a, t2b) + fmaxf(0.f, 3.f * sA);
    if (sA > 0.01f) {
        const float inv = 1.0f / (4.0f * sA);
        kL = fmaxf(kL, (LO - cD - sA * hbase) * inv);
        kU = fminf(kU, (HI - cC - sA * hbase) * inv);
    } else if (sA < -0.01f) {
        const float inv = 1.0f / (4.0f * sA);
        kL = fmaxf(kL, (HI - cC - sA * hbase) * inv);
        kU = fminf(kU, (LO - cD - sA * hbase) * inv);
    }
    const int k0 = max(0, (int)floorf(kL));
    const int k1 = min(HCH / 4, (int)floorf(kU) + 1);

    float acc0 = 0.f, acc1 = 0.f, acc2 = 0.f, acc3 = 0.f;
    const unsigned m = 0xFFFFFFFFu;

    if (k0 < k1) {
        float hf = hbase + (float)hl + 4.0f * (float)k0;

        float colv = fmaf(sA, hf, colw);
        float rowv = fmaf(sB, hf, roww);
        float cf = floorf(colv), rf = floorf(rowv);
        uint4 qT, qB;
        ldg256(img + (int)fmaf(rf, (float)PW, cf), qT, qB);
        float fc = colv - cf, fr = rowv - rf;

        for (int k = k0; k < k1; ++k) {
            hf += 4.0f;
            const float colv2 = fmaf(sA, hf, colw);
            const float rowv2 = fmaf(sB, hf, roww);
            const float cf2 = floorf(colv2), rf2 = floorf(rowv2);
            uint4 nT, nB;
            ldg256(img + (int)fmaf(rf2, (float)PW, cf2), nT, nB);

            const float gc = 1.f - fc, gr = 1.f - fr;
            const float w00 = gr * gc, w01 = gr * fc, w10 = fr * gc, w11 = fr * fc;
            const float2 t0 = __half22float2(*(const __half2*)&qT.x);
            const float2 t1 = __half22float2(*(const __half2*)&qT.y);
            const float2 t2 = __half22float2(*(const __half2*)&qT.z);
            const float2 t3 = __half22float2(*(const __half2*)&qT.w);
            const float2 b0 = __half22float2(*(const __half2*)&qB.x);
            const float2 b1 = __half22float2(*(const __half2*)&qB.y);
            const float2 b2 = __half22float2(*(const __half2*)&qB.z);
            const float2 b3 = __half22float2(*(const __half2*)&qB.w);

            float vx = fmaf(t0.x, w00, fmaf(t0.y, w01, fmaf(b0.x, w10, b0.y * w11)));
            float vy = fmaf(t1.x, w00, fmaf(t1.y, w01, fmaf(b1.x, w10, b1.y * w11)));
            float vz = fmaf(t2.x, w00, fmaf(t2.y, w01, fmaf(b2.x, w10, b2.y * w11)));
            float vw = fmaf(t3.x, w00, fmaf(t3.y, w01, fmaf(b3.x, w10, b3.y * w11)));

            acc0 += vx; acc1 += vy; acc2 += vz; acc3 += vw;

            // row partial: fp16 pack + 1-level exchange + pair store
            __half2 h01 = __floats2half2_rn(vx, vy);
            __half2 h23 = __floats2half2_rn(vz, vw);
            unsigned u01 = *(unsigned*)&h01;
            unsigned u23 = *(unsigned*)&h23;
            unsigned r01 = __shfl_xor_sync(m, u01, 1);
            unsigned r23 = __shfl_xor_sync(m, u23, 1);
            __half2 s01 = __hadd2(h01, *(__half2*)&r01);
            __half2 s23 = __hadd2(h23, *(__half2*)&r23);
            if ((wl & 1) == 0)
                s_row[warp][hl + 4 * k][wl >> 1] =
                    make_uint2(*(unsigned*)&s01, *(unsigned*)&s23);

            qT = nT; qB = nB;
            fc = colv2 - cf2;
            fr = rowv2 - rf2;
        }
    }

    // column partial: reduce 4 h-sublanes, one packed STG.128
    acc0 += __shfl_xor_sync(m, acc0, 8);  acc1 += __shfl_xor_sync(m, acc1, 8);
    acc2 += __shfl_xor_sync(m, acc2, 8);  acc3 += __shfl_xor_sync(m, acc3, 8);
    acc0 += __shfl_xor_sync(m, acc0, 16); acc1 += __shfl_xor_sync(m, acc1, 16);
    acc2 += __shfl_xor_sync(m, acc2, 16); acc3 += __shfl_xor_sync(m, acc3, 16);
    if (hl == 0)
        g_colpart[ch][t][w] = make_float4(acc0, acc1, acc2, acc3);

    // row partial tail: sum 8 warps x 4 pairpos, store half4
    __syncthreads();
    if (tid < HCH) {
        float s0 = 0.f, s1 = 0.f, s2 = 0.f, s3 = 0.f;
        #pragma unroll
        for (int wp = 0; wp < 8; ++wp) {
            const uint4* rowp = (const uint4*)&s_row[wp][tid][0];
            #pragma unroll
            for (int q = 0; q < 2; ++q) {
                uint4 u = rowp[q];
                float2 a01 = __half22float2(*(const __half2*)&u.x);
                float2 a23 = __half22float2(*(const __half2*)&u.y);
                float2 c01 = __half22float2(*(const __half2*)&u.z);
                float2 c23 = __half22float2(*(const __half2*)&u.w);
                s0 += a01.x + c01.x; s1 += a01.y + c01.y;
                s2 += a23.x + c23.x; s3 += a23.y + c23.y;
            }
        }
        const int h = ch * HCH + tid;
        __half2 o01 = __floats2half2_rn(s0, s1);
        __half2 o23 = __floats2half2_rn(s2, s3);
        g_rowpart[t][wt][h] = make_uint2(*(unsigned*)&o01, *(unsigned*)&o23);
    }
}

// ---------------------------------------------------------------------------
// Reduce: two threads per (t,w) (lane pairs via bit 0); each sums half the
// partials, combine with shfl_xor(1). p==0 lane stores all 4 batch outputs.
// ---------------------------------------------------------------------------
__global__ void reduce_kernel(float* __restrict__ out) {
    int idx = blockIdx.x * blockDim.x + threadIdx.x;   // (t*IW + w)*2 + p
    if (idx >= NT * IW * 2) return;
    const int p  = idx & 1;
    const int tw = idx >> 1;
    const int w  = tw & (IW - 1);
    const int t  = tw >> 9;

    float s0 = 0.f, s1 = 0.f, s2 = 0.f, s3 = 0.f;
    if (t < NTH) {
        #pragma unroll
        for (int i = 0; i < NCH / 2; ++i) {
            float4 v = g_colpart[p * (NCH / 2) + i][t][w];
            s0 += v.x; s1 += v.y; s2 += v.z; s3 += v.w;
        }
    } else {
        const int th = t - NTH;
        const int h  = IW - 1 - w;
        #pragma unroll
        for (int i = 0; i < NWT / 2; ++i) {
            uint2 u = g_rowpart[th][p * (NWT / 2) + i][h];
            float2 v01 = __half22float2(*(const __half2*)&u.x);
            float2 v23 = __half22float2(*(const __half2*)&u.y);
            s0 += v01.x; s1 += v01.y; s2 += v23.x; s3 += v23.y;
        }
    }
    const unsigned m = 0xFFFFFFFFu;
    s0 += __shfl_xor_sync(m, s0, 1);
    s1 += __shfl_xor_sync(m, s1, 1);
    s2 += __shfl_xor_sync(m, s2, 1);
    s3 += __shfl_xor_sync(m, s3, 1);

    if (p == 0) {
        const int o = w * NT + t;
        out[o]               = s0;
        out[o +     IW * NT] = s1;
        out[o + 2 * IW * NT] = s2;
        out[o + 3 * IW * NT] = s3;
    }
}

// ---------------------------------------------------------------------------
extern "C" void kernel_launch(void* const* d_in, const int* in_sizes, int n_in,
                              void* d_out, int out_size) {
    const float* x  = (const float*)d_in[0];
    const float* th = (const float*)d_in[1];
    if (n_in >= 2 && in_sizes[0] == NT) {
        const float* tmp = x; x = th; th = tmp;
    }
    float* out = (float*)d_out;

    dim3 pgrid(PW / 32, PW / 32);      // 17 x 17
    prep_kernel<<<pgrid, 1024>>>(x);

    dim3 grid(NTH, NWT, NCH);
    radon_kernel<<<grid, 256>>>(th);

    reduce_kernel<<<(NT * IW * 2 + 255) / 256, 256>>>(out);
}

// round 17
// speedup vs baseline: 1.0341x; 1.0341x over previous
#include <cuda_runtime.h>
#include <cuda_fp16.h>

#define IW   512
#define NB   4
#define NT   180
#define NTH  90             // sampled angles; 90..179 via row sums
#define PAD  16
#define PW   (IW + 2*PAD)   // 544 = 17*32
#define NCH  4
#define HCH  (IW / NCH)     // 128
#define NWT  8
#define IMG_STRIDE (IW*IW)
#define OFS  ((float)PAD + 255.5f)     // padded-center offset
#define LO   ((float)PAD - 1.0f)       // nonzero support lower edge
#define HI   ((float)PAD + 512.0f)     // nonzero support upper edge

// 32B entry at (r,c): full 2x2 bilinear stencil x 4 batches, fp16.
struct __align__(32) E32 { uint4 t, b; };

__device__ E32   g_pair [PW * PW];                 // 9.5 MB
__device__ E32   g_pairT[PW * PW];                 // 9.5 MB
__device__ float4 g_colpart[NCH][NTH][IW];         // batches packed per entry
__device__ uint2  g_rowpart[NTH][NWT][IW];         // half4 per (t,wt,h)

// 256-bit global load (sm_100+)
__device__ __forceinline__ void ldg256(const E32* p, uint4& t, uint4& b) {
    asm("ld.global.v8.b32 {%0,%1,%2,%3,%4,%5,%6,%7}, [%8];"
        : "=r"(t.x), "=r"(t.y), "=r"(t.z), "=r"(t.w),
          "=r"(b.x), "=r"(b.y), "=r"(b.z), "=r"(b.w)
        : "l"(p));
}

// ---------------------------------------------------------------------------
// Tiled prep, 1024 threads: one 32x32-entry tile per block.
// ---------------------------------------------------------------------------
__global__ __launch_bounds__(1024) void prep_kernel(const float* __restrict__ x) {
    __shared__ float s[4][33 * 33];     // 17.4 KB

    const int Rp0 = blockIdx.y * 32;
    const int Cp0 = blockIdx.x * 32;
    const int pr0 = Rp0 - PAD;
    const int pc0 = Cp0 - PAD;
    const int tid = threadIdx.x;

    for (int k = tid; k < 33 * 33; k += 1024) {
        const int i = k / 33;
        const int j = k - i * 33;
        const int pr = pr0 + i;
        const int pc = pc0 + j;
        const bool v = (unsigned)pr < (unsigned)IW && (unsigned)pc < (unsigned)IW;
        const int off = pr * IW + pc;
        #pragma unroll
        for (int b = 0; b < 4; ++b)
            s[b][k] = v ? x[off + b * IMG_STRIDE] : 0.f;
    }
    __syncthreads();

    {   // normal-orientation entry: (i, j), j fastest
        const int i = tid >> 5, j = tid & 31;
        E32 en;
        #pragma unroll
        for (int b = 0; b < 4; ++b) {
            const float p00 = s[b][i * 33 + j];
            const float p01 = s[b][i * 33 + j + 1];
            const float p10 = s[b][(i + 1) * 33 + j];
            const float p11 = s[b][(i + 1) * 33 + j + 1];
            __half2 nt = __floats2half2_rn(p00, p01);
            __half2 nb = __floats2half2_rn(p10, p11);
            ((unsigned*)&en.t)[b] = *(unsigned*)&nt;
            ((unsigned*)&en.b)[b] = *(unsigned*)&nb;
        }
        g_pair[(Rp0 + i) * PW + (Cp0 + j)] = en;
    }

    {   // transposed-orientation entry: (j, i), i fastest
        const int j = tid >> 5, i = tid & 31;
        E32 et;
        #pragma unroll
        for (int b = 0; b < 4; ++b) {
            const float p00 = s[b][i * 33 + j];
            const float p01 = s[b][i * 33 + j + 1];
            const float p10 = s[b][(i + 1) * 33 + j];
            const float p11 = s[b][(i + 1) * 33 + j + 1];
            __half2 tt = __floats2half2_rn(p00, p10);
            __half2 tb = __floats2half2_rn(p01, p11);
            ((unsigned*)&et.t)[b] = *(unsigned*)&tt;
            ((unsigned*)&et.b)[b] = *(unsigned*)&tb;
        }
        g_pairT[(Cp0 + j) * PW + (Rp0 + i)] = et;
    }
}

// ---------------------------------------------------------------------------
// Radon for t in 0..89; column sums -> P_t, row sums -> P_{t+90} (mirrored).
// Row partials: 2-level fp16 exchange -> 16KB slab -> 7 CTAs/SM.
// ---------------------------------------------------------------------------
__global__ __launch_bounds__(256, 7) void radon_kernel(const float* __restrict__ theta) {
    // s_row[warp][h][quadpos] : uint2 = (half2 b01, half2 b23), 4-lane sums (16KB)
    __shared__ uint2 s_row[8][HCH][2];

    const int t    = blockIdx.x;
    const int wt   = blockIdx.y;
    const int ch   = blockIdx.z;
    const int tid  = threadIdx.x;
    const int warp = tid >> 5;
    const int lane = tid & 31;
    const int wl   = lane & 7;
    const int hl   = lane >> 3;
    const int w    = wt * 64 + warp * 8 + wl;

    // zero row-partial slab (skipped k's must read as 0): 1024 uint4 total
    {
        uint4* sr = (uint4*)&s_row[0][0][0];
        #pragma unroll
        for (int i = 0; i < 4; ++i)
            sr[tid + 256 * i] = make_uint4(0u, 0u, 0u, 0u);
    }
    __syncthreads();

    const float rad = theta[t] * 0.017453292519943295f;
    float s, c;
    sincosf(rad, &s, &c);

    float cA, sA, cB, sB;
    const E32* __restrict__ img;
    if (fabsf(s) > fabsf(c)) { cA = -s; sA = c; cB = c;  sB = s; img = g_pairT; }
    else                     { cA = c;  sA = s; cB = -s; sB = c; img = g_pair;  }

    const float wf    = (float)w - 255.5f;
    const float colw  = fmaf(cA, wf, OFS);
    const float roww  = fmaf(cB, wf, OFS);
    const float hbase = (float)(ch * HCH) - 255.5f;

    // warp-uniform valid-k interval (nonzero bilinear support: coord in (LO, HI))
    const float wfa = (float)(wt * 64 + warp * 8) - 255.5f;
    const float wfb = wfa + 7.0f;
    float t1a = cB * wfa, t1b = cB * wfb;
    const float rA = OFS + fminf(t1a, t1b);
    const float rB = OFS + fmaxf(t1a, t1b) + 3.0f * sB;
    const float rh = sB * hbase;
    const float inv4sB = 1.0f / (4.0f * sB);
    float kL = (LO - rB - rh) * inv4sB;
    float kU = (HI - rA - rh) * inv4sB;
    float t2a = cA * wfa, t2b = cA * wfb;
    const float cC = OFS + fminf(t2a, t2b) + fminf(0.f, 3.f * sA);
    const float cD = OFS + fmaxf(t2a, t2b) + fmaxf(0.f, 3.f * sA);
    if (sA > 0.01f) {
        const float inv = 1.0f / (4.0f * sA);
        kL = fmaxf(kL, (LO - cD - sA * hbase) * inv);
        kU = fminf(kU, (HI - cC - sA * hbase) * inv);
    } else if (sA < -0.01f) {
        const float inv = 1.0f / (4.0f * sA);
        kL = fmaxf(kL, (HI - cC - sA * hbase) * inv);
        kU = fminf(kU, (LO - cD - sA * hbase) * inv);
    }
    const int k0 = max(0, (int)floorf(kL));
    const int k1 = min(HCH / 4, (int)floorf(kU) + 1);

    float acc0 = 0.f, acc1 = 0.f, acc2 = 0.f, acc3 = 0.f;
    const unsigned m = 0xFFFFFFFFu;

    if (k0 < k1) {
        float hf = hbase + (float)hl + 4.0f * (float)k0;

        float colv = fmaf(sA, hf, colw);
        float rowv = fmaf(sB, hf, roww);
        float cf = floorf(colv), rf = floorf(rowv);
        uint4 qT, qB;
        ldg256(img + (int)fmaf(rf, (float)PW, cf), qT, qB);
        float fc = colv - cf, fr = rowv - rf;

        for (int k = k0; k < k1; ++k) {
            hf += 4.0f;
            const float colv2 = fmaf(sA, hf, colw);
            const float rowv2 = fmaf(sB, hf, roww);
            const float cf2 = floorf(colv2), rf2 = floorf(rowv2);
            uint4 nT, nB;
            ldg256(img + (int)fmaf(rf2, (float)PW, cf2), nT, nB);

            const float gc = 1.f - fc, gr = 1.f - fr;
            const float w00 = gr * gc, w01 = gr * fc, w10 = fr * gc, w11 = fr * fc;
            const float2 t0 = __half22float2(*(const __half2*)&qT.x);
            const float2 t1 = __half22float2(*(const __half2*)&qT.y);
            const float2 t2 = __half22float2(*(const __half2*)&qT.z);
            const float2 t3 = __half22float2(*(const __half2*)&qT.w);
            const float2 b0 = __half22float2(*(const __half2*)&qB.x);
            const float2 b1 = __half22float2(*(const __half2*)&qB.y);
            const float2 b2 = __half22float2(*(const __half2*)&qB.z);
            const float2 b3 = __half22float2(*(const __half2*)&qB.w);

            float vx = fmaf(t0.x, w00, fmaf(t0.y, w01, fmaf(b0.x, w10, b0.y * w11)));
            float vy = fmaf(t1.x, w00, fmaf(t1.y, w01, fmaf(b1.x, w10, b1.y * w11)));
            float vz = fmaf(t2.x, w00, fmaf(t2.y, w01, fmaf(b2.x, w10, b2.y * w11)));
            float vw = fmaf(t3.x, w00, fmaf(t3.y, w01, fmaf(b3.x, w10, b3.y * w11)));

            acc0 += vx; acc1 += vy; acc2 += vz; acc3 += vw;

            // row partial: fp16 pack + 2-level exchange + quad store
            __half2 h01 = __floats2half2_rn(vx, vy);
            __half2 h23 = __floats2half2_rn(vz, vw);
            unsigned u01 = *(unsigned*)&h01;
            unsigned u23 = *(unsigned*)&h23;
            unsigned r01 = __shfl_xor_sync(m, u01, 1);
            unsigned r23 = __shfl_xor_sync(m, u23, 1);
            __half2 s01 = __hadd2(h01, *(__half2*)&r01);
            __half2 s23 = __hadd2(h23, *(__half2*)&r23);
            unsigned q01 = __shfl_xor_sync(m, *(unsigned*)&s01, 2);
            unsigned q23 = __shfl_xor_sync(m, *(unsigned*)&s23, 2);
            __half2 z01 = __hadd2(s01, *(__half2*)&q01);
            __half2 z23 = __hadd2(s23, *(__half2*)&q23);
            if ((wl & 3) == 0)
                s_row[warp][hl + 4 * k][wl >> 2] =
                    make_uint2(*(unsigned*)&z01, *(unsigned*)&z23);

            qT = nT; qB = nB;
            fc = colv2 - cf2;
            fr = rowv2 - rf2;
        }
    }

    // column partial: reduce 4 h-sublanes, one packed STG.128
    acc0 += __shfl_xor_sync(m, acc0, 8);  acc1 += __shfl_xor_sync(m, acc1, 8);
    acc2 += __shfl_xor_sync(m, acc2, 8);  acc3 += __shfl_xor_sync(m, acc3, 8);
    acc0 += __shfl_xor_sync(m, acc0, 16); acc1 += __shfl_xor_sync(m, acc1, 16);
    acc2 += __shfl_xor_sync(m, acc2, 16); acc3 += __shfl_xor_sync(m, acc3, 16);
    if (hl == 0)
        g_colpart[ch][t][w] = make_float4(acc0, acc1, acc2, acc3);

    // row partial tail: sum 8 warps x 2 quadpos (one uint4 per warp), store half4
    __syncthreads();
    if (tid < HCH) {
        float s0 = 0.f, s1 = 0.f, s2 = 0.f, s3 = 0.f;
        #pragma unroll
        for (int wp = 0; wp < 8; ++wp) {
            uint4 u = *(const uint4*)&s_row[wp][tid][0];
            float2 a01 = __half22float2(*(const __half2*)&u.x);
            float2 a23 = __half22float2(*(const __half2*)&u.y);
            float2 c01 = __half22float2(*(const __half2*)&u.z);
            float2 c23 = __half22float2(*(const __half2*)&u.w);
            s0 += a01.x + c01.x; s1 += a01.y + c01.y;
            s2 += a23.x + c23.x; s3 += a23.y + c23.y;
        }
        const int h = ch * HCH + tid;
        __half2 o01 = __floats2half2_rn(s0, s1);
        __half2 o23 = __floats2half2_rn(s2, s3);
        g_rowpart[t][wt][h] = make_uint2(*(unsigned*)&o01, *(unsigned*)&o23);
    }
}

// ---------------------------------------------------------------------------
// Reduce: two threads per (t,w); halves combined with shfl_xor(1).
// ---------------------------------------------------------------------------
__global__ void reduce_kernel(float* __restrict__ out) {
    int idx = blockIdx.x * blockDim.x + threadIdx.x;   // (t*IW + w)*2 + p
    if (idx >= NT * IW * 2) return;
    const int p  = idx & 1;
    const int tw = idx >> 1;
    const int w  = tw & (IW - 1);
    const int t  = tw >> 9;

    float s0 = 0.f, s1 = 0.f, s2 = 0.f, s3 = 0.f;
    if (t < NTH) {
        #pragma unroll
        for (int i = 0; i < NCH / 2; ++i) {
            float4 v = g_colpart[p * (NCH / 2) + i][t][w];
            s0 += v.x; s1 += v.y; s2 += v.z; s3 += v.w;
        }
    } else {
        const int th = t - NTH;
        const int h  = IW - 1 - w;
        #pragma unroll
        for (int i = 0; i < NWT / 2; ++i) {
            uint2 u = g_rowpart[th][p * (NWT / 2) + i][h];
            float2 v01 = __half22float2(*(const __half2*)&u.x);
            float2 v23 = __half22float2(*(const __half2*)&u.y);
            s0 += v01.x; s1 += v01.y; s2 += v23.x; s3 += v23.y;
        }
    }
    const unsigned m = 0xFFFFFFFFu;
    s0 += __shfl_xor_sync(m, s0, 1);
    s1 += __shfl_xor_sync(m, s1, 1);
    s2 += __shfl_xor_sync(m, s2, 1);
    s3 += __shfl_xor_sync(m, s3, 1);

    if (p == 0) {
        const int o = w * NT + t;
        out[o]               = s0;
        out[o +     IW * NT] = s1;
        out[o + 2 * IW * NT] = s2;
        out[o + 3 * IW * NT] = s3;
    }
}

// ---------------------------------------------------------------------------
extern "C" void kernel_launch(void* const* d_in, const int* in_sizes, int n_in,
                              void* d_out, int out_size) {
    const float* x  = (const float*)d_in[0];
    const float* th = (const float*)d_in[1];
    if (n_in >= 2 && in_sizes[0] == NT) {
        const float* tmp = x; x = th; th = tmp;
    }
    float* out = (float*)d_out;

    dim3 pgrid(PW / 32, PW / 32);      // 17 x 17
    prep_kernel<<<pgrid, 1024>>>(x);

    dim3 grid(NTH, NWT, NCH);
    radon_kernel<<<grid, 256>>>(th);

    reduce_kernel<<<(NT * IW * 2 + 255) / 256, 256>>>(out);
}